// round 7
// baseline (speedup 1.0000x reference)
#include <cuda_runtime.h>
#include <math.h>

// Problem constants (fixed shapes: L=5, B=8, n=1024, d=64)
#define LNUM 5
#define BNUM 8
#define NLB  (LNUM * BNUM)       // 40
#define N    1024
#define D    64
#define S    8                   // n-dim splits per (l,b)
#define ROWS (N / S)             // 128 rows per chunk
#define TR   64                  // smem tile rows
#define TRP  68                  // padded row count (16B-aligned col stride, bank-staggered)
#define GSZ  (D * D)             // 4096
#define STRIDE (3 * GSZ + 2 * D) // per-chunk scratch: XX, YY, XY, sx, sy

__device__ float g_part[NLB * S * STRIDE];   // ~15.9 MB scratch
__device__ float g_sums[NLB * 8 * 3];        // per (lb, slice): sXX, sYY, sXY

typedef unsigned long long u64;

// packed f32x2 FMA: acc.lo += a.lo*b.lo ; acc.hi += a.hi*b.hi
#define FMA2(acc, a, b) \
    asm("fma.rn.f32x2 %0, %1, %2, %0;" : "+l"(acc) : "l"(a), "l"(b))

static __device__ __forceinline__ float unpk_sum(u64 v) {
    float2 f;
    asm("mov.b64 {%0, %1}, %2;" : "=f"(f.x), "=f"(f.y) : "l"(v));
    return f.x + f.y;
}

// ---------------------------------------------------------------------------
// Kernel A: per (l,b,chunk,jhalf) partial Grams, K-packed FFMA2 on a
// TRANSPOSED smem tile (Xs_t[col][row], pad 68).
//   Thread (ig = tid>>3 in 0..15, jg = tid&7) owns i-cols {ig+16*ii} and
//   j-cols {32*jc + jg + 8*jj}, ii,jj in 0..3.  Per 4-row group: 16 LDS.128
//   (each 1 wavefront: distinct banks via stride-68 staggering) + 96 FFMA2.
//   Accumulators are f32x2 (even/odd K partials); epilogue adds lo+hi.
// grid = NLB * S * 2 = 640 blocks.
// ---------------------------------------------------------------------------
__global__ void __launch_bounds__(128, 3) cka_partial_kernel(
    const float* __restrict__ X, const float* __restrict__ Y)
{
    __shared__ float Xs[D * TRP];
    __shared__ float Ys[D * TRP];
    __shared__ float red[128];

    const int tid = threadIdx.x;
    const int w = tid >> 5;
    const int l = tid & 31;
    const int bx = blockIdx.x;
    const int lb = bx >> 4;
    const int rem = bx & 15;
    const int chunk = rem >> 1;
    const int jc = rem & 1;

    const int ig = tid >> 3;        // 0..15  -> i-cols ig + 16*ii
    const int jg = tid & 7;         // 0..7   -> j-cols 32*jc + jg + 8*jj

    // transpose-load mapping: 4x4 blocks
    const int c4 = (l & 3) + 4 * (w & 1);    // 0..7  (col-quad, +8p later)
    const int r4 = (l >> 2) + 8 * (w >> 1);  // 0..15 (row-quad)

    const float* xb = X + (size_t)lb * N * D + (size_t)chunk * ROWS * D;
    const float* yb = Y + (size_t)lb * N * D + (size_t)chunk * ROWS * D;

    u64 aXX[4][4] = {};
    u64 aYY[4][4] = {};
    u64 aXY[4][4] = {};
    float csx = 0.f, csy = 0.f;
    const int col  = tid & 63;      // column-sum ownership
    const int half = tid >> 6;      // 2 row groups of 32

    #pragma unroll
    for (int t = 0; t < ROWS / TR; ++t) {
        __syncthreads();   // protect smem from previous iteration's readers

        // transposed cooperative load: 4x4 register transpose blocks
        #pragma unroll
        for (int mat = 0; mat < 2; ++mat) {
            const float4* g4 = (const float4*)((mat ? yb : xb) + t * TR * D);
            float* dst = mat ? Ys : Xs;
            #pragma unroll
            for (int p = 0; p < 2; ++p) {
                int cc = c4 + 8 * p;             // col-quad 0..15
                float4 v0 = g4[(4 * r4 + 0) * 16 + cc];
                float4 v1 = g4[(4 * r4 + 1) * 16 + cc];
                float4 v2 = g4[(4 * r4 + 2) * 16 + cc];
                float4 v3 = g4[(4 * r4 + 3) * 16 + cc];
                float* db = dst + 4 * r4;
                *(float4*)(db + (4 * cc + 0) * TRP) = {v0.x, v1.x, v2.x, v3.x};
                *(float4*)(db + (4 * cc + 1) * TRP) = {v0.y, v1.y, v2.y, v3.y};
                *(float4*)(db + (4 * cc + 2) * TRP) = {v0.z, v1.z, v2.z, v3.z};
                *(float4*)(db + (4 * cc + 3) * TRP) = {v0.w, v1.w, v2.w, v3.w};
            }
        }
        __syncthreads();

        #pragma unroll 2
        for (int rg = 0; rg < TR / 4; ++rg) {
            const float* px = Xs + 4 * rg;
            const float* py = Ys + 4 * rg;
            u64 xi0[4], xi1[4], yi0[4], yi1[4];
            u64 xj0[4], xj1[4], yj0[4], yj1[4];
            #pragma unroll
            for (int ii = 0; ii < 4; ++ii) {
                double2 dx = *(const double2*)(px + (ig + 16 * ii) * TRP);
                double2 dy = *(const double2*)(py + (ig + 16 * ii) * TRP);
                xi0[ii] = __double_as_longlong(dx.x);
                xi1[ii] = __double_as_longlong(dx.y);
                yi0[ii] = __double_as_longlong(dy.x);
                yi1[ii] = __double_as_longlong(dy.y);
            }
            #pragma unroll
            for (int jj = 0; jj < 4; ++jj) {
                int jcol = 32 * jc + jg + 8 * jj;
                double2 dx = *(const double2*)(px + jcol * TRP);
                double2 dy = *(const double2*)(py + jcol * TRP);
                xj0[jj] = __double_as_longlong(dx.x);
                xj1[jj] = __double_as_longlong(dx.y);
                yj0[jj] = __double_as_longlong(dy.x);
                yj1[jj] = __double_as_longlong(dy.y);
            }
            #pragma unroll
            for (int ii = 0; ii < 4; ++ii)
                #pragma unroll
                for (int jj = 0; jj < 4; ++jj) {
                    FMA2(aXX[ii][jj], xi0[ii], xj0[jj]);
                    FMA2(aXX[ii][jj], xi1[ii], xj1[jj]);
                    FMA2(aXY[ii][jj], xi0[ii], yj0[jj]);
                    FMA2(aXY[ii][jj], xi1[ii], yj1[jj]);
                    FMA2(aYY[ii][jj], yi0[ii], yj0[jj]);
                    FMA2(aYY[ii][jj], yi1[ii], yj1[jj]);
                }
        }

        // column-sum partials (transposed layout: contiguous per column)
        if (jc == 0) {
            const float* cx = Xs + col * TRP + half * 32;
            const float* cy = Ys + col * TRP + half * 32;
            #pragma unroll
            for (int k = 0; k < 8; ++k) {
                float4 vx = *(const float4*)(cx + 4 * k);
                float4 vy = *(const float4*)(cy + 4 * k);
                csx += (vx.x + vx.y) + (vx.z + vx.w);
                csy += (vy.x + vy.y) + (vy.z + vy.w);
            }
        }
    }

    float* out = g_part + (size_t)(lb * S + chunk) * STRIDE;

    if (jc == 0) {
        red[tid] = csx;
        __syncthreads();
        if (tid < 64) out[3 * GSZ + tid] = red[tid] + red[tid + 64];
        __syncthreads();
        red[tid] = csy;
        __syncthreads();
        if (tid < 64) out[3 * GSZ + 64 + tid] = red[tid] + red[tid + 64];
    }

    // epilogue: scalar stores (strided ownership), rows i = ig+16ii,
    // cols j = 32jc + jg + 8jj
    #pragma unroll
    for (int ii = 0; ii < 4; ++ii) {
        int i = ig + 16 * ii;
        #pragma unroll
        for (int jj = 0; jj < 4; ++jj) {
            int j = 32 * jc + jg + 8 * jj;
            out[i * D + j]           = unpk_sum(aXX[ii][jj]);
            out[GSZ + i * D + j]     = unpk_sum(aYY[ii][jj]);
            out[2 * GSZ + i * D + j] = unpk_sum(aXY[ii][jj]);
        }
    }
}

// ---------------------------------------------------------------------------
// Kernel B: per (lb, slice-of-8) reduce S chunk-partials, apply rank-1
// centering correction, partial Frobenius-square-reduce.
// grid = NLB * 8 = 320 blocks, 128 threads, float4 loads.
// ---------------------------------------------------------------------------
__global__ void __launch_bounds__(128) cka_reduce_kernel()
{
    const int lb = blockIdx.x >> 3;
    const int slice = blockIdx.x & 7;
    const int tid = threadIdx.x;
    __shared__ float sx[D], sy[D];
    __shared__ float red[128];

    const float* base = g_part + (size_t)lb * S * STRIDE;

    if (tid < 64) {
        float ax = 0.f, ay = 0.f;
        #pragma unroll
        for (int s = 0; s < S; ++s) {
            ax += base[s * STRIDE + 3 * GSZ + tid];
            ay += base[s * STRIDE + 3 * GSZ + 64 + tid];
        }
        sx[tid] = ax;
        sy[tid] = ay;
    }
    __syncthreads();

    const float inv_n = 1.0f / (float)N;
    const int f4i = slice * 128 + tid;   // float4 index within a 64x64 matrix
    const int i  = f4i >> 4;             // row
    const int jb = (f4i & 15) * 4;       // first column of the float4

    const float sxi = sx[i] * inv_n;
    const float syi = sy[i] * inv_n;
    const float4 sxj = *(const float4*)&sx[jb];
    const float4 syj = *(const float4*)&sy[jb];

    float4 gxx = {0,0,0,0}, gyy = {0,0,0,0}, gxy = {0,0,0,0};
    #pragma unroll
    for (int s = 0; s < S; ++s) {
        const float4* p = (const float4*)(base + (size_t)s * STRIDE);
        float4 v;
        v = p[f4i];
        gxx.x += v.x; gxx.y += v.y; gxx.z += v.z; gxx.w += v.w;
        v = p[1024 + f4i];
        gyy.x += v.x; gyy.y += v.y; gyy.z += v.z; gyy.w += v.w;
        v = p[2048 + f4i];
        gxy.x += v.x; gxy.y += v.y; gxy.z += v.z; gxy.w += v.w;
    }

    gxx.x -= sxi * sxj.x; gxx.y -= sxi * sxj.y; gxx.z -= sxi * sxj.z; gxx.w -= sxi * sxj.w;
    gyy.x -= syi * syj.x; gyy.y -= syi * syj.y; gyy.z -= syi * syj.z; gyy.w -= syi * syj.w;
    gxy.x -= sxi * syj.x; gxy.y -= sxi * syj.y; gxy.z -= sxi * syj.z; gxy.w -= sxi * syj.w;

    float vXX = gxx.x*gxx.x + gxx.y*gxx.y + gxx.z*gxx.z + gxx.w*gxx.w;
    float vYY = gyy.x*gyy.x + gyy.y*gyy.y + gyy.z*gyy.z + gyy.w*gyy.w;
    float vXY = gxy.x*gxy.x + gxy.y*gxy.y + gxy.z*gxy.z + gxy.w*gxy.w;

    float* gs = g_sums + (size_t)(lb * 8 + slice) * 3;

    red[tid] = vXX;
    __syncthreads();
    for (int off = 64; off > 0; off >>= 1) {
        if (tid < off) red[tid] += red[tid + off];
        __syncthreads();
    }
    if (tid == 0) gs[0] = red[0];
    __syncthreads();

    red[tid] = vYY;
    __syncthreads();
    for (int off = 64; off > 0; off >>= 1) {
        if (tid < off) red[tid] += red[tid + off];
        __syncthreads();
    }
    if (tid == 0) gs[1] = red[0];
    __syncthreads();

    red[tid] = vXY;
    __syncthreads();
    for (int off = 64; off > 0; off >>= 1) {
        if (tid < off) red[tid] += red[tid + off];
        __syncthreads();
    }
    if (tid == 0) gs[2] = red[0];
}

// ---------------------------------------------------------------------------
// Kernel C: final scalar loss = mean_l( -log( mean_b ratio + eps ) )
// ---------------------------------------------------------------------------
__global__ void cka_final_kernel(float* __restrict__ out)
{
    __shared__ float ratio[NLB];
    const int tid = threadIdx.x;
    if (tid < NLB) {
        float txx = 0.f, tyy = 0.f, txy = 0.f;
        #pragma unroll
        for (int s2 = 0; s2 < 8; ++s2) {
            const float* g = g_sums + (size_t)(tid * 8 + s2) * 3;
            txx += g[0];
            tyy += g[1];
            txy += g[2];
        }
        ratio[tid] = fabsf(txy) / (sqrtf(txx) * sqrtf(tyy));
    }
    __syncthreads();
    if (tid == 0) {
        float loss = 0.f;
        #pragma unroll
        for (int l = 0; l < LNUM; ++l) {
            float m = 0.f;
            #pragma unroll
            for (int b = 0; b < BNUM; ++b)
                m += ratio[l * BNUM + b];
            m *= (1.0f / (float)BNUM);
            loss += -logf(m + 1e-8f);
        }
        out[0] = loss * (1.0f / (float)LNUM);
    }
}

extern "C" void kernel_launch(void* const* d_in, const int* in_sizes, int n_in,
                              void* d_out, int out_size)
{
    const float* teacher = (const float*)d_in[0];
    const float* student = (const float*)d_in[1];
    float* out = (float*)d_out;

    cka_partial_kernel<<<NLB * S * 2, 128>>>(teacher, student);
    cka_reduce_kernel<<<NLB * 8, 128>>>();
    cka_final_kernel<<<1, 64>>>(out);
}

// round 8
// speedup vs baseline: 1.1606x; 1.1606x over previous
#include <cuda_runtime.h>
#include <math.h>

// Problem constants (fixed shapes: L=5, B=8, n=1024, d=64)
#define LNUM 5
#define BNUM 8
#define NLB  (LNUM * BNUM)       // 40
#define N    1024
#define D    64
#define S    16                  // n-dim splits per (l,b)
#define ROWS (N / S)             // 64 rows per chunk (single smem tile)
#define GSZ  (D * D)             // 4096
#define STRIDE (3 * GSZ + 2 * D) // per-chunk scratch: XX, YY, XY, sx, sy

__device__ float g_part[NLB * S * STRIDE];   // ~31.8 MB scratch
__device__ float g_sums[NLB * 8 * 3];        // per (lb, slice): sXX, sYY, sXY

typedef unsigned long long u64;

// packed f32x2 FMA: acc.lo += a.lo*b.lo ; acc.hi += a.hi*b.hi
#define FMA2(acc, a, b) \
    asm("fma.rn.f32x2 %0, %1, %2, %0;" : "+l"(acc) : "l"(a), "l"(b))

static __device__ __forceinline__ u64 bcast2(float v) {
    u64 r;
    asm("mov.b64 %0, {%1, %1};" : "=l"(r) : "f"(v));
    return r;
}

static __device__ __forceinline__ float2 unpk2(u64 v) {
    float2 f;
    asm("mov.b64 {%0, %1}, %2;" : "=f"(f.x), "=f"(f.y) : "l"(v));
    return f;
}

// ---------------------------------------------------------------------------
// Kernel A: per (l,b,chunk,jhalf) partial Grams with packed FFMA2.
// 128 threads; thread tile 4(i) x 4(j), j-cols as two f32x2 lanes.
// One 64-row tile per block. grid = NLB * S * 2 = 1280 blocks (fine blocks
// -> 5 resident blocks/SM with a deep refill queue for latency hiding).
// ---------------------------------------------------------------------------
__global__ void __launch_bounds__(128, 5) cka_partial_kernel(
    const float* __restrict__ X, const float* __restrict__ Y)
{
    __shared__ float Xs[ROWS * D];
    __shared__ float Ys[ROWS * D];
    __shared__ float red[128];

    const int tid = threadIdx.x;
    const int tx = tid & 15;        // i-cols: 4*tx .. 4*tx+3 (contiguous)
    const int ty = tid >> 4;        // 0..7 -> j-cols: 32*jc + 4*ty .. +3
    const int bx = blockIdx.x;
    const int lb = bx >> 5;
    const int rem = bx & 31;
    const int chunk = rem >> 1;
    const int jc = rem & 1;

    const float* xb = X + (size_t)lb * N * D + (size_t)chunk * ROWS * D;
    const float* yb = Y + (size_t)lb * N * D + (size_t)chunk * ROWS * D;

    // accumulators: [a][pair], each u64 holds 2 packed f32 j-lanes
    u64 aXX[4][2] = {};
    u64 aYY[4][2] = {};
    u64 aXY[4][2] = {};
    float csx = 0.f, csy = 0.f;
    const int col  = tid & 63;      // column-sum ownership
    const int half = tid >> 6;      // 2 row groups of 32

    // cooperative vectorized tile load: ROWS*D floats = 1024 float4 each
    {
        const float4* xs4 = (const float4*)xb;
        const float4* ys4 = (const float4*)yb;
        float4* Xs4 = (float4*)Xs;
        float4* Ys4 = (float4*)Ys;
        #pragma unroll
        for (int k = 0; k < (ROWS * D / 4) / 128; ++k) {
            Xs4[tid + 128 * k] = xs4[tid + 128 * k];
            Ys4[tid + 128 * k] = ys4[tid + 128 * k];
        }
    }
    __syncthreads();

    #pragma unroll 8
    for (int r = 0; r < ROWS; ++r) {
        const float* rowX = Xs + r * D;
        const float* rowY = Ys + r * D;
        // j operands: naturally packed f32 pairs via 16B loads
        double2 xj = ((const double2*)(rowX + 32 * jc))[ty];
        double2 yj = ((const double2*)(rowY + 32 * jc))[ty];
        u64 xj0 = __double_as_longlong(xj.x);
        u64 xj1 = __double_as_longlong(xj.y);
        u64 yj0 = __double_as_longlong(yj.x);
        u64 yj1 = __double_as_longlong(yj.y);
        // i operands: 4 scalars each, broadcast-packed
        float4 xi = ((const float4*)rowX)[tx];
        float4 yi = ((const float4*)rowY)[tx];
        float xiA[4] = {xi.x, xi.y, xi.z, xi.w};
        float yiA[4] = {yi.x, yi.y, yi.z, yi.w};
        #pragma unroll
        for (int a = 0; a < 4; ++a) {
            u64 xb2 = bcast2(xiA[a]);
            u64 yb2 = bcast2(yiA[a]);
            FMA2(aXX[a][0], xb2, xj0);
            FMA2(aXX[a][1], xb2, xj1);
            FMA2(aXY[a][0], xb2, yj0);
            FMA2(aXY[a][1], xb2, yj1);
            FMA2(aYY[a][0], yb2, yj0);
            FMA2(aYY[a][1], yb2, yj1);
        }
    }

    // column-sum partials (only jc==0 blocks; uniform branch)
    if (jc == 0) {
        #pragma unroll 8
        for (int rr = 0; rr < ROWS / 2; ++rr) {
            int r = half * (ROWS / 2) + rr;
            csx += Xs[r * D + col];
            csy += Ys[r * D + col];
        }
    }

    float* out = g_part + (size_t)(lb * S + chunk) * STRIDE;

    if (jc == 0) {
        red[tid] = csx;
        __syncthreads();
        if (tid < 64) out[3 * GSZ + tid] = red[tid] + red[tid + 64];
        __syncthreads();
        red[tid] = csy;
        __syncthreads();
        if (tid < 64) out[3 * GSZ + 64 + tid] = red[tid] + red[tid + 64];
    }

    // float4 stores of unpacked accumulator pairs
    #pragma unroll
    for (int a = 0; a < 4; ++a) {
        int i = 4 * tx + a;
        int j = 32 * jc + 4 * ty;
        float2 x0 = unpk2(aXX[a][0]), x1 = unpk2(aXX[a][1]);
        float2 y0 = unpk2(aYY[a][0]), y1 = unpk2(aYY[a][1]);
        float2 z0 = unpk2(aXY[a][0]), z1 = unpk2(aXY[a][1]);
        float4 vxx = {x0.x, x0.y, x1.x, x1.y};
        float4 vyy = {y0.x, y0.y, y1.x, y1.y};
        float4 vxy = {z0.x, z0.y, z1.x, z1.y};
        *(float4*)(out + i * D + j)           = vxx;
        *(float4*)(out + GSZ + i * D + j)     = vyy;
        *(float4*)(out + 2 * GSZ + i * D + j) = vxy;
    }
}

// ---------------------------------------------------------------------------
// Kernel B: per (lb, slice-of-8) reduce S chunk-partials, apply rank-1
// centering correction, partial Frobenius-square-reduce.
// grid = NLB * 8 = 320 blocks, 128 threads, float4 loads.
// ---------------------------------------------------------------------------
__global__ void __launch_bounds__(128) cka_reduce_kernel()
{
    const int lb = blockIdx.x >> 3;
    const int slice = blockIdx.x & 7;
    const int tid = threadIdx.x;
    __shared__ float sx[D], sy[D];
    __shared__ float red[128];

    const float* base = g_part + (size_t)lb * S * STRIDE;

    if (tid < 64) {
        float ax = 0.f, ay = 0.f;
        #pragma unroll
        for (int s = 0; s < S; ++s) {
            ax += base[s * STRIDE + 3 * GSZ + tid];
            ay += base[s * STRIDE + 3 * GSZ + 64 + tid];
        }
        sx[tid] = ax;
        sy[tid] = ay;
    }
    __syncthreads();

    const float inv_n = 1.0f / (float)N;
    const int f4i = slice * 128 + tid;   // float4 index within a 64x64 matrix
    const int i  = f4i >> 4;             // row
    const int jb = (f4i & 15) * 4;       // first column of the float4

    const float sxi = sx[i] * inv_n;
    const float syi = sy[i] * inv_n;
    const float4 sxj = *(const float4*)&sx[jb];
    const float4 syj = *(const float4*)&sy[jb];

    float4 gxx = {0,0,0,0}, gyy = {0,0,0,0}, gxy = {0,0,0,0};
    #pragma unroll
    for (int s = 0; s < S; ++s) {
        const float4* p = (const float4*)(base + (size_t)s * STRIDE);
        float4 v;
        v = p[f4i];
        gxx.x += v.x; gxx.y += v.y; gxx.z += v.z; gxx.w += v.w;
        v = p[1024 + f4i];
        gyy.x += v.x; gyy.y += v.y; gyy.z += v.z; gyy.w += v.w;
        v = p[2048 + f4i];
        gxy.x += v.x; gxy.y += v.y; gxy.z += v.z; gxy.w += v.w;
    }

    gxx.x -= sxi * sxj.x; gxx.y -= sxi * sxj.y; gxx.z -= sxi * sxj.z; gxx.w -= sxi * sxj.w;
    gyy.x -= syi * syj.x; gyy.y -= syi * syj.y; gyy.z -= syi * syj.z; gyy.w -= syi * syj.w;
    gxy.x -= sxi * syj.x; gxy.y -= sxi * syj.y; gxy.z -= sxi * syj.z; gxy.w -= sxi * syj.w;

    float vXX = gxx.x*gxx.x + gxx.y*gxx.y + gxx.z*gxx.z + gxx.w*gxx.w;
    float vYY = gyy.x*gyy.x + gyy.y*gyy.y + gyy.z*gyy.z + gyy.w*gyy.w;
    float vXY = gxy.x*gxy.x + gxy.y*gxy.y + gxy.z*gxy.z + gxy.w*gxy.w;

    float* gs = g_sums + (size_t)(lb * 8 + slice) * 3;

    red[tid] = vXX;
    __syncthreads();
    for (int off = 64; off > 0; off >>= 1) {
        if (tid < off) red[tid] += red[tid + off];
        __syncthreads();
    }
    if (tid == 0) gs[0] = red[0];
    __syncthreads();

    red[tid] = vYY;
    __syncthreads();
    for (int off = 64; off > 0; off >>= 1) {
        if (tid < off) red[tid] += red[tid + off];
        __syncthreads();
    }
    if (tid == 0) gs[1] = red[0];
    __syncthreads();

    red[tid] = vXY;
    __syncthreads();
    for (int off = 64; off > 0; off >>= 1) {
        if (tid < off) red[tid] += red[tid + off];
        __syncthreads();
    }
    if (tid == 0) gs[2] = red[0];
}

// ---------------------------------------------------------------------------
// Kernel C: final scalar loss = mean_l( -log( mean_b ratio + eps ) )
// ---------------------------------------------------------------------------
__global__ void cka_final_kernel(float* __restrict__ out)
{
    __shared__ float ratio[NLB];
    const int tid = threadIdx.x;
    if (tid < NLB) {
        float txx = 0.f, tyy = 0.f, txy = 0.f;
        #pragma unroll
        for (int s2 = 0; s2 < 8; ++s2) {
            const float* g = g_sums + (size_t)(tid * 8 + s2) * 3;
            txx += g[0];
            tyy += g[1];
            txy += g[2];
        }
        ratio[tid] = fabsf(txy) / (sqrtf(txx) * sqrtf(tyy));
    }
    __syncthreads();
    if (tid == 0) {
        float loss = 0.f;
        #pragma unroll
        for (int l = 0; l < LNUM; ++l) {
            float m = 0.f;
            #pragma unroll
            for (int b = 0; b < BNUM; ++b)
                m += ratio[l * BNUM + b];
            m *= (1.0f / (float)BNUM);
            loss += -logf(m + 1e-8f);
        }
        out[0] = loss * (1.0f / (float)LNUM);
    }
}

extern "C" void kernel_launch(void* const* d_in, const int* in_sizes, int n_in,
                              void* d_out, int out_size)
{
    const float* teacher = (const float*)d_in[0];
    const float* student = (const float*)d_in[1];
    float* out = (float*)d_out;

    cka_partial_kernel<<<NLB * S * 2, 128>>>(teacher, student);
    cka_reduce_kernel<<<NLB * 8, 128>>>();
    cka_final_kernel<<<1, 64>>>(out);
}

// round 10
// speedup vs baseline: 2.0127x; 1.7342x over previous
#include <cuda_runtime.h>
#include <cuda_bf16.h>
#include <math.h>
#include <stdint.h>

// Problem constants (fixed shapes: L=5, B=8, n=1024, d=64)
#define LNUM 5
#define BNUM 8
#define NLB  40
#define N    1024
#define D    64
#define S    8                   // n-dim chunks (128 rows each)
#define KR   128                 // n-rows per chunk
#define KB   256                 // bf16 K rows (hi + lo)
#define PITCH  72                // bf16 units per T row (pad: conflict-free ldmatrix)
#define PITCHB 144               // bytes per T row
#define GSZ  4096
#define STRIDE (3 * GSZ + 2 * D) // per-chunk scratch: XX, YY, XY, sx, sy

__device__ float g_part[NLB * S * STRIDE];
__device__ float g_sums[NLB * 8 * 3];

#define T_BYTES  (KB * PITCHB)       // 36864
#define SMEM_DYN (2 * T_BYTES)       // 73728

__device__ __forceinline__ uint32_t smem_u32(const void* p) {
    uint32_t a;
    asm("{ .reg .u64 t; cvta.to.shared.u64 t, %1; cvt.u32.u64 %0, t; }" : "=r"(a) : "l"(p));
    return a;
}

// ldmatrix x4 transposed (b16): pairs run along the k (row) dimension of T
#define LDSM4T(r, a) \
    asm volatile("ldmatrix.sync.aligned.m8n8.x4.trans.shared.b16 {%0,%1,%2,%3}, [%4];" \
        : "=r"((r)[0]), "=r"((r)[1]), "=r"((r)[2]), "=r"((r)[3]) : "r"(a))

// D += A * B  (m16n8k16, bf16 in, f32 accumulate)
#define MMA_BF16(c, a, b0, b1) \
    asm volatile("mma.sync.aligned.m16n8k16.row.col.f32.bf16.bf16.f32 " \
        "{%0,%1,%2,%3}, {%4,%5,%6,%7}, {%8,%9}, {%0,%1,%2,%3};" \
        : "+f"((c)[0]), "+f"((c)[1]), "+f"((c)[2]), "+f"((c)[3]) \
        : "r"((a)[0]), "r"((a)[1]), "r"((a)[2]), "r"((a)[3]), "r"(b0), "r"(b1))

// ---------------------------------------------------------------------------
// Kernel A: per (lb, 128-row chunk) Grams XtX, YtY, XtY via bf16 hi/lo
// mma.sync (exact to ~2^-17). T = [hi(M); lo(M)] : 256 x 64 bf16, pitch 72.
// 4 warps; warp w owns gram rows 16w..16w+15, full n=64.
// grid = 40*8 = 320 blocks, 128 threads.
// ---------------------------------------------------------------------------
__global__ void __launch_bounds__(128) cka_gram_kernel(
    const float* __restrict__ Xg, const float* __restrict__ Yg)
{
    extern __shared__ char smem[];
    char* Tx = smem;
    char* Ty = smem + T_BYTES;
    const int tid = threadIdx.x;
    const int w = tid >> 5, l = tid & 31;
    const int lb = blockIdx.x >> 3, ks = blockIdx.x & 7;

    const float* xb = Xg + (size_t)lb * N * D + (size_t)ks * KR * D;
    const float* yb = Yg + (size_t)lb * N * D + (size_t)ks * KR * D;

    // ---- load + hi/lo bf16 convert into T tiles ----
    #pragma unroll
    for (int mat = 0; mat < 2; ++mat) {
        const float4* g4 = (const float4*)(mat ? yb : xb);
        char* T = mat ? Ty : Tx;
        #pragma unroll
        for (int it = 0; it < 16; ++it) {
            int idx = tid + 128 * it;
            int n = idx >> 4, dq = idx & 15;
            float4 v = g4[idx];
            uint32_t h01, h23, l01, l23;
            asm("cvt.rn.bf16x2.f32 %0, %1, %2;" : "=r"(h01) : "f"(v.y), "f"(v.x));
            asm("cvt.rn.bf16x2.f32 %0, %1, %2;" : "=r"(h23) : "f"(v.w), "f"(v.z));
            float r0 = v.x - __uint_as_float(h01 << 16);
            float r1 = v.y - __uint_as_float(h01 & 0xffff0000u);
            float r2 = v.z - __uint_as_float(h23 << 16);
            float r3 = v.w - __uint_as_float(h23 & 0xffff0000u);
            asm("cvt.rn.bf16x2.f32 %0, %1, %2;" : "=r"(l01) : "f"(r1), "f"(r0));
            asm("cvt.rn.bf16x2.f32 %0, %1, %2;" : "=r"(l23) : "f"(r3), "f"(r2));
            uint2 hv; hv.x = h01; hv.y = h23;
            uint2 lv; lv.x = l01; lv.y = l23;
            *(uint2*)(T + n * PITCHB + 8 * dq) = hv;            // hi rows 0..127
            *(uint2*)(T + (n + 128) * PITCHB + 8 * dq) = lv;    // lo rows 128..255
        }
    }
    __syncthreads();

    float* out = g_part + (size_t)(lb * S + ks) * STRIDE;

    // ---- column sums (sum of hi+lo rows == sum of x to 2^-17) ----
    if (tid < 64) {
        int p = tid & 31;                       // col pair {2p, 2p+1}
        const char* T = (tid < 32) ? Tx : Ty;
        float s0 = 0.f, s1 = 0.f;
        #pragma unroll 8
        for (int r = 0; r < 256; ++r) {
            uint32_t u = *(const uint32_t*)(T + r * PITCHB + 4 * p);
            s0 += __uint_as_float(u << 16);
            s1 += __uint_as_float(u & 0xffff0000u);
        }
        float* o = out + 3 * GSZ + ((tid < 32) ? 0 : 64) + 2 * p;
        o[0] = s0;
        o[1] = s1;
    }

    // ---- MMA mainloop ----
    const uint32_t sTx = smem_u32(Tx), sTy = smem_u32(Ty);
    const int g = l >> 3, ri = l & 7;
    // A-frag tile order: (m0,k0)(m8,k0)(m0,k8)(m8,k8) ->
    //   T rows: k0 | k0 | k8 | k8 ; T cols: c | c+8 | c | c+8
    const uint32_t offA = (uint32_t)((((g >> 1) & 1) * 8 + ri) * PITCHB
                                     + (g & 1) * 16 + (16 * w) * 2);
    // B-frag tile order: (k0,n0)(k8,n0)(k0,n8)(k8,n8)
    const uint32_t offB = (uint32_t)(((g & 1) * 8 + ri) * PITCHB
                                     + ((g >> 1) & 1) * 16);

    float cXX[8][4] = {}, cXY[8][4] = {}, cYY[8][4] = {};

    #pragma unroll 2
    for (int kk = 0; kk < 16; ++kk) {
        uint32_t kb = (uint32_t)(kk * 16 * PITCHB);
        uint32_t ax[4], ay[4];
        LDSM4T(ax, sTx + offA + kb);
        LDSM4T(ay, sTy + offA + kb);
        #pragma unroll
        for (int nt = 0; nt < 4; ++nt) {
            uint32_t bx[4], by[4];
            LDSM4T(bx, sTx + offB + kb + 32 * nt);
            LDSM4T(by, sTy + offB + kb + 32 * nt);
            MMA_BF16(cXX[2 * nt],     ax, bx[0], bx[1]);
            MMA_BF16(cXX[2 * nt + 1], ax, bx[2], bx[3]);
            MMA_BF16(cXY[2 * nt],     ax, by[0], by[1]);
            MMA_BF16(cXY[2 * nt + 1], ax, by[2], by[3]);
            MMA_BF16(cYY[2 * nt],     ay, by[0], by[1]);
            MMA_BF16(cYY[2 * nt + 1], ay, by[2], by[3]);
        }
    }

    // ---- epilogue: c-frag -> g_part ----
    {
        int r0 = 16 * w + (l >> 2);
        int c0 = 2 * (l & 3);
        #pragma unroll
        for (int f = 0; f < 8; ++f) {
            int col = 8 * f + c0;
            float2 v;
            v.x = cXX[f][0]; v.y = cXX[f][1];
            *(float2*)(out + r0 * 64 + col) = v;
            v.x = cXX[f][2]; v.y = cXX[f][3];
            *(float2*)(out + (r0 + 8) * 64 + col) = v;
            v.x = cYY[f][0]; v.y = cYY[f][1];
            *(float2*)(out + GSZ + r0 * 64 + col) = v;
            v.x = cYY[f][2]; v.y = cYY[f][3];
            *(float2*)(out + GSZ + (r0 + 8) * 64 + col) = v;
            v.x = cXY[f][0]; v.y = cXY[f][1];
            *(float2*)(out + 2 * GSZ + r0 * 64 + col) = v;
            v.x = cXY[f][2]; v.y = cXY[f][3];
            *(float2*)(out + 2 * GSZ + (r0 + 8) * 64 + col) = v;
        }
    }
}

// ---------------------------------------------------------------------------
// Kernel B: per (lb, slice-of-8) reduce S chunk-partials, apply rank-1
// centering correction, partial Frobenius-square-reduce.
// ---------------------------------------------------------------------------
__global__ void __launch_bounds__(128) cka_reduce_kernel()
{
    const int lb = blockIdx.x >> 3;
    const int slice = blockIdx.x & 7;
    const int tid = threadIdx.x;
    __shared__ float sx[D], sy[D];
    __shared__ float red[128];

    const float* base = g_part + (size_t)lb * S * STRIDE;

    if (tid < 64) {
        float ax = 0.f, ay = 0.f;
        #pragma unroll
        for (int s = 0; s < S; ++s) {
            ax += base[s * STRIDE + 3 * GSZ + tid];
            ay += base[s * STRIDE + 3 * GSZ + 64 + tid];
        }
        sx[tid] = ax;
        sy[tid] = ay;
    }
    __syncthreads();

    const float inv_n = 1.0f / (float)N;
    const int f4i = slice * 128 + tid;
    const int i = f4i >> 4;
    const int jb = (f4i & 15) * 4;

    const float sxi = sx[i] * inv_n;
    const float syi = sy[i] * inv_n;
    const float4 sxj = *(const float4*)&sx[jb];
    const float4 syj = *(const float4*)&sy[jb];

    float4 gxx = {0, 0, 0, 0}, gyy = {0, 0, 0, 0}, gxy = {0, 0, 0, 0};
    #pragma unroll
    for (int s = 0; s < S; ++s) {
        const float4* p = (const float4*)(base + (size_t)s * STRIDE);
        float4 v;
        v = p[f4i];
        gxx.x += v.x; gxx.y += v.y; gxx.z += v.z; gxx.w += v.w;
        v = p[1024 + f4i];
        gyy.x += v.x; gyy.y += v.y; gyy.z += v.z; gyy.w += v.w;
        v = p[2048 + f4i];
        gxy.x += v.x; gxy.y += v.y; gxy.z += v.z; gxy.w += v.w;
    }

    gxx.x -= sxi * sxj.x; gxx.y -= sxi * sxj.y; gxx.z -= sxi * sxj.z; gxx.w -= sxi * sxj.w;
    gyy.x -= syi * syj.x; gyy.y -= syi * syj.y; gyy.z -= syi * syj.z; gyy.w -= syi * syj.w;
    gxy.x -= sxi * syj.x; gxy.y -= sxi * syj.y; gxy.z -= sxi * syj.z; gxy.w -= sxi * syj.w;

    float vXX = gxx.x * gxx.x + gxx.y * gxx.y + gxx.z * gxx.z + gxx.w * gxx.w;
    float vYY = gyy.x * gyy.x + gyy.y * gyy.y + gyy.z * gyy.z + gyy.w * gyy.w;
    float vXY = gxy.x * gxy.x + gxy.y * gxy.y + gxy.z * gxy.z + gxy.w * gxy.w;

    float* gs = g_sums + (size_t)(lb * 8 + slice) * 3;

    red[tid] = vXX;
    __syncthreads();
    for (int off = 64; off > 0; off >>= 1) {
        if (tid < off) red[tid] += red[tid + off];
        __syncthreads();
    }
    if (tid == 0) gs[0] = red[0];
    __syncthreads();

    red[tid] = vYY;
    __syncthreads();
    for (int off = 64; off > 0; off >>= 1) {
        if (tid < off) red[tid] += red[tid + off];
        __syncthreads();
    }
    if (tid == 0) gs[1] = red[0];
    __syncthreads();

    red[tid] = vXY;
    __syncthreads();
    for (int off = 64; off > 0; off >>= 1) {
        if (tid < off) red[tid] += red[tid + off];
        __syncthreads();
    }
    if (tid == 0) gs[2] = red[0];
}

// ---------------------------------------------------------------------------
// Kernel C: final scalar loss = mean_l( -log( mean_b ratio + eps ) )
// ---------------------------------------------------------------------------
__global__ void cka_final_kernel(float* __restrict__ out)
{
    __shared__ float ratio[NLB];
    const int tid = threadIdx.x;
    if (tid < NLB) {
        float txx = 0.f, tyy = 0.f, txy = 0.f;
        #pragma unroll
        for (int s2 = 0; s2 < 8; ++s2) {
            const float* g = g_sums + (size_t)(tid * 8 + s2) * 3;
            txx += g[0];
            tyy += g[1];
            txy += g[2];
        }
        ratio[tid] = fabsf(txy) / (sqrtf(txx) * sqrtf(tyy));
    }
    __syncthreads();
    if (tid == 0) {
        float loss = 0.f;
        #pragma unroll
        for (int l = 0; l < LNUM; ++l) {
            float m = 0.f;
            #pragma unroll
            for (int b = 0; b < BNUM; ++b)
                m += ratio[l * BNUM + b];
            m *= (1.0f / (float)BNUM);
            loss += -logf(m + 1e-8f);
        }
        out[0] = loss * (1.0f / (float)LNUM);
    }
}

extern "C" void kernel_launch(void* const* d_in, const int* in_sizes, int n_in,
                              void* d_out, int out_size)
{
    const float* teacher = (const float*)d_in[0];
    const float* student = (const float*)d_in[1];
    float* out = (float*)d_out;

    cudaFuncSetAttribute(cka_gram_kernel,
                         cudaFuncAttributeMaxDynamicSharedMemorySize, SMEM_DYN);
    cka_gram_kernel<<<NLB * S, 128, SMEM_DYN>>>(teacher, student);
    cka_reduce_kernel<<<NLB * 8, 128>>>();
    cka_final_kernel<<<1, 64>>>(out);
}